// round 3
// baseline (speedup 1.0000x reference)
#include <cuda_runtime.h>
#include <cuda_fp16.h>
#include <cstdint>
#include <cstddef>

#define IN_F  1024
#define OUT_F 1024
#define POP   64

#define BM 128
#define BN 128
#define BK 16

// Scratch: effective weight / bias (device globals — no allocation allowed)
__device__ float g_weff[(size_t)OUT_F * IN_F];
__device__ float g_beff[OUT_F];

// ---------------------------------------------------------------------------
// Kernel 1: w_eff[j,k] = weight[j,k] + sum_i scale[i] * wp[i,j,k]
// wp is FP32 on device (harness upcasts the fp16 input). Each thread owns 4
// consecutive elements; one float4 load per population member (MLP via unroll).
// ---------------------------------------------------------------------------
__global__ void reduce_weight_kernel(const float* __restrict__ weight,
                                     const float* __restrict__ scale,
                                     const float* __restrict__ wp) {
    __shared__ float s_scale[POP];
    if (threadIdx.x < POP) s_scale[threadIdx.x] = scale[threadIdx.x];
    __syncthreads();

    size_t base = ((size_t)blockIdx.x * blockDim.x + threadIdx.x) * 4;
    if (base >= (size_t)OUT_F * IN_F) return;

    float4 acc = *reinterpret_cast<const float4*>(weight + base);

#pragma unroll 8
    for (int i = 0; i < POP; i++) {
        const float s = s_scale[i];
        float4 p = *reinterpret_cast<const float4*>(wp + (size_t)i * (OUT_F * IN_F) + base);
        acc.x += s * p.x;
        acc.y += s * p.y;
        acc.z += s * p.z;
        acc.w += s * p.w;
    }
    *reinterpret_cast<float4*>(g_weff + base) = acc;
}

// ---------------------------------------------------------------------------
// Kernel 2: b_eff[j] = bias[j] + sum_i scale[i] * bp[i,j]   (bp is FP32 too)
// ---------------------------------------------------------------------------
__global__ void reduce_bias_kernel(const float* __restrict__ bias,
                                   const float* __restrict__ scale,
                                   const float* __restrict__ bp) {
    int j = blockIdx.x * blockDim.x + threadIdx.x;
    if (j >= OUT_F) return;
    float acc = bias[j];
#pragma unroll 8
    for (int i = 0; i < POP; i++)
        acc += scale[i] * bp[i * OUT_F + j];
    g_beff[j] = acc;
}

// ---------------------------------------------------------------------------
// Kernel 3: out[m, n] = sum_k x[m,k] * w_eff[n,k] + b_eff[n]
// Classic 128x128x16 smem-tiled SGEMM, 256 threads, 8x8 per thread
// with 4+4 split row/col groups (conflict-free LDS.128 in the mainloop).
// ---------------------------------------------------------------------------
__global__ __launch_bounds__(256, 2)
void gemm_kernel(const float* __restrict__ X, float* __restrict__ out) {
    __shared__ float As[BK][BM];   // [k][m]
    __shared__ float Bs[BK][BN];   // [k][n]

    const int tid = threadIdx.x;
    const int ty  = tid >> 4;      // 0..15 (row group)
    const int tx  = tid & 15;      // 0..15 (col group)
    const int m0  = blockIdx.y * BM;
    const int n0  = blockIdx.x * BN;

    float acc[8][8];
#pragma unroll
    for (int i = 0; i < 8; i++)
#pragma unroll
        for (int j = 0; j < 8; j++) acc[i][j] = 0.0f;

    for (int k0 = 0; k0 < IN_F; k0 += BK) {
        // Load tiles (512 float4 total per operand; 2 per thread), transposed
        // into [k][row] layout so mainloop reads are contiguous.
#pragma unroll
        for (int l = 0; l < 2; l++) {
            int f  = tid + l * 256;
            int r  = f >> 2;            // 0..127
            int kc = (f & 3) << 2;      // 0,4,8,12
            float4 va = *reinterpret_cast<const float4*>(
                X + (size_t)(m0 + r) * IN_F + k0 + kc);
            As[kc + 0][r] = va.x; As[kc + 1][r] = va.y;
            As[kc + 2][r] = va.z; As[kc + 3][r] = va.w;
            float4 vb = *reinterpret_cast<const float4*>(
                g_weff + (size_t)(n0 + r) * IN_F + k0 + kc);
            Bs[kc + 0][r] = vb.x; Bs[kc + 1][r] = vb.y;
            Bs[kc + 2][r] = vb.z; Bs[kc + 3][r] = vb.w;
        }
        __syncthreads();

#pragma unroll
        for (int kk = 0; kk < BK; kk++) {
            float4 a0 = *reinterpret_cast<const float4*>(&As[kk][ty * 4]);
            float4 a1 = *reinterpret_cast<const float4*>(&As[kk][64 + ty * 4]);
            float4 b0 = *reinterpret_cast<const float4*>(&Bs[kk][tx * 4]);
            float4 b1 = *reinterpret_cast<const float4*>(&Bs[kk][64 + tx * 4]);
            float a[8] = {a0.x, a0.y, a0.z, a0.w, a1.x, a1.y, a1.z, a1.w};
            float b[8] = {b0.x, b0.y, b0.z, b0.w, b1.x, b1.y, b1.z, b1.w};
#pragma unroll
            for (int i = 0; i < 8; i++)
#pragma unroll
                for (int j = 0; j < 8; j++)
                    acc[i][j] += a[i] * b[j];
        }
        __syncthreads();
    }

    // Epilogue: add bias, write 2 float4 per row
    float4 bv0 = *reinterpret_cast<const float4*>(&g_beff[n0 + tx * 4]);
    float4 bv1 = *reinterpret_cast<const float4*>(&g_beff[n0 + 64 + tx * 4]);
    float bb[8] = {bv0.x, bv0.y, bv0.z, bv0.w, bv1.x, bv1.y, bv1.z, bv1.w};

#pragma unroll
    for (int i = 0; i < 8; i++) {
        int m = m0 + ((i < 4) ? (ty * 4 + i) : (64 + ty * 4 + (i - 4)));
        float4 o0 = make_float4(acc[i][0] + bb[0], acc[i][1] + bb[1],
                                acc[i][2] + bb[2], acc[i][3] + bb[3]);
        float4 o1 = make_float4(acc[i][4] + bb[4], acc[i][5] + bb[5],
                                acc[i][6] + bb[6], acc[i][7] + bb[7]);
        *reinterpret_cast<float4*>(out + (size_t)m * OUT_F + n0 + tx * 4)      = o0;
        *reinterpret_cast<float4*>(out + (size_t)m * OUT_F + n0 + 64 + tx * 4) = o1;
    }
}

// ---------------------------------------------------------------------------
// Launch.
// Inputs identified BY ELEMENT COUNT (all six unique), order-independent:
//   x: 16777216 (fp32)           weight: 1048576 (fp32)   bias: 1024 (fp32)
//   scale: 64 (fp32)             weight_perturbations: 67108864 (fp32 — harness
//   upcasts fp16)                bias_perturbations: 65536 (fp32, same reason)
// ---------------------------------------------------------------------------
extern "C" void kernel_launch(void* const* d_in, const int* in_sizes, int n_in,
                              void* d_out, int out_size) {
    const float* x      = nullptr;
    const float* weight = nullptr;
    const float* bias   = nullptr;
    const float* scale  = nullptr;
    const float* wp     = nullptr;
    const float* bp     = nullptr;

    for (int i = 0; i < n_in; i++) {
        switch (in_sizes[i]) {
            case 16777216: x      = (const float*)d_in[i]; break;
            case 1048576:  weight = (const float*)d_in[i]; break;
            case 1024:     bias   = (const float*)d_in[i]; break;
            case 64:       scale  = (const float*)d_in[i]; break;
            case 67108864: wp     = (const float*)d_in[i]; break;
            case 65536:    bp     = (const float*)d_in[i]; break;
            default: break;
        }
    }

    float* out = (float*)d_out;
    const int M = 16777216 / IN_F;   // 16384 rows

    {
        int total_threads = (OUT_F * IN_F) / 4;      // 262144
        reduce_weight_kernel<<<total_threads / 256, 256>>>(weight, scale, wp);
    }
    reduce_bias_kernel<<<(OUT_F + 255) / 256, 256>>>(bias, scale, bp);

    dim3 grid(OUT_F / BN, M / BM);
    gemm_kernel<<<grid, 256>>>(x, out);
}

// round 5
// speedup vs baseline: 3.1010x; 3.1010x over previous
#include <cuda_runtime.h>
#include <cuda_bf16.h>
#include <cstdint>
#include <cstddef>

#define IN_F   1024
#define OUT_F  1024
#define POP    64
#define MROWS  16384

#define BM 128
#define BN 256
#define BK 32
#define GEMM_THREADS 256

// smem stage layout (bf16 rows of 32 + 8 pad = 80B row stride; conflict-free ldmatrix)
#define A_HI_OFF 0
#define A_LO_OFF 10240
#define B_HI_OFF 20480
#define B_LO_OFF 40960
#define STAGE_SZ 61440
#define NSTAGE   3
#define SMEM_TOTAL (NSTAGE * STAGE_SZ)   // 184320 B

// ---------------- scratch (device globals; allocation is forbidden) --------
__device__ __align__(16) __nv_bfloat16 g_x_hi[(size_t)MROWS * IN_F];
__device__ __align__(16) __nv_bfloat16 g_x_lo[(size_t)MROWS * IN_F];
__device__ __align__(16) __nv_bfloat16 g_w_hi[(size_t)OUT_F * IN_F];
__device__ __align__(16) __nv_bfloat16 g_w_lo[(size_t)OUT_F * IN_F];
__device__ float g_beff[OUT_F];

// ---------------- PTX helpers (all portable to plain sm_103 target) --------
__device__ __forceinline__ uint32_t smem_u32(const void* p) {
    uint32_t a;
    asm("{ .reg .u64 t; cvta.to.shared.u64 t, %1; cvt.u32.u64 %0, t; }" : "=r"(a) : "l"(p));
    return a;
}
#define CP16(dst_u32, gptr) \
    asm volatile("cp.async.cg.shared.global [%0], [%1], 16;" :: "r"(dst_u32), "l"(gptr) : "memory")
#define CP_COMMIT() asm volatile("cp.async.commit_group;" ::: "memory")
#define CP_WAIT1()  asm volatile("cp.async.wait_group 1;" ::: "memory")
#define CP_WAIT0()  asm volatile("cp.async.wait_group 0;" ::: "memory")

#define LDSM4(r0, r1, r2, r3, addr)                                              \
    asm volatile("ldmatrix.sync.aligned.m8n8.x4.shared.b16 {%0,%1,%2,%3}, [%4];" \
        : "=r"(r0), "=r"(r1), "=r"(r2), "=r"(r3) : "r"(addr))

__device__ __forceinline__ void mma16816(float* d, const uint32_t* a, const uint32_t* b) {
    asm volatile(
        "mma.sync.aligned.m16n8k16.row.col.f32.bf16.bf16.f32 "
        "{%0,%1,%2,%3}, {%4,%5,%6,%7}, {%8,%9}, {%0,%1,%2,%3};"
        : "+f"(d[0]), "+f"(d[1]), "+f"(d[2]), "+f"(d[3])
        : "r"(a[0]), "r"(a[1]), "r"(a[2]), "r"(a[3]), "r"(b[0]), "r"(b[1]));
}

// ---------------------------------------------------------------------------
// Prep 1: w_eff = weight + sum_i s_i*wp_i (fp32), emitted as bf16 hi/lo split
// ---------------------------------------------------------------------------
__global__ void reduce_weight_kernel(const float* __restrict__ weight,
                                     const float* __restrict__ scale,
                                     const float* __restrict__ wp) {
    __shared__ float s_scale[POP];
    if (threadIdx.x < POP) s_scale[threadIdx.x] = scale[threadIdx.x];
    __syncthreads();

    size_t base = ((size_t)blockIdx.x * blockDim.x + threadIdx.x) * 4;
    float4 acc = *reinterpret_cast<const float4*>(weight + base);
#pragma unroll 8
    for (int i = 0; i < POP; i++) {
        const float s = s_scale[i];
        float4 p = *reinterpret_cast<const float4*>(wp + (size_t)i * (OUT_F * IN_F) + base);
        acc.x += s * p.x; acc.y += s * p.y; acc.z += s * p.z; acc.w += s * p.w;
    }
    float v[4] = {acc.x, acc.y, acc.z, acc.w};
    __nv_bfloat16 hi[4], lo[4];
#pragma unroll
    for (int q = 0; q < 4; q++) {
        hi[q] = __float2bfloat16(v[q]);
        lo[q] = __float2bfloat16(v[q] - __bfloat162float(hi[q]));
    }
    *reinterpret_cast<uint2*>(g_w_hi + base) = *reinterpret_cast<uint2*>(hi);
    *reinterpret_cast<uint2*>(g_w_lo + base) = *reinterpret_cast<uint2*>(lo);
}

// ---------------------------------------------------------------------------
// Prep 2: split x into bf16 hi/lo
// ---------------------------------------------------------------------------
__global__ void split_x_kernel(const float* __restrict__ x) {
    size_t base = ((size_t)blockIdx.x * blockDim.x + threadIdx.x) * 8;
    float4 a = *reinterpret_cast<const float4*>(x + base);
    float4 b = *reinterpret_cast<const float4*>(x + base + 4);
    float v[8] = {a.x, a.y, a.z, a.w, b.x, b.y, b.z, b.w};
    __nv_bfloat16 hi[8], lo[8];
#pragma unroll
    for (int q = 0; q < 8; q++) {
        hi[q] = __float2bfloat16(v[q]);
        lo[q] = __float2bfloat16(v[q] - __bfloat162float(hi[q]));
    }
    *reinterpret_cast<uint4*>(g_x_hi + base) = *reinterpret_cast<uint4*>(hi);
    *reinterpret_cast<uint4*>(g_x_lo + base) = *reinterpret_cast<uint4*>(lo);
}

// ---------------------------------------------------------------------------
// Prep 3: bias
// ---------------------------------------------------------------------------
__global__ void reduce_bias_kernel(const float* __restrict__ bias,
                                   const float* __restrict__ scale,
                                   const float* __restrict__ bp) {
    int j = blockIdx.x * blockDim.x + threadIdx.x;
    if (j >= OUT_F) return;
    float acc = bias[j];
#pragma unroll 8
    for (int i = 0; i < POP; i++) acc += scale[i] * bp[i * OUT_F + j];
    g_beff[j] = acc;
}

// ---------------------------------------------------------------------------
// GEMM via mma.sync (portable HMMA): out = x @ w_eff^T + b_eff
// 3-pass split-bf16: acc += xh*wh + xh*wl + xl*wh  (fp32 accumulators).
// CTA 128x256x32, 8 warps (2x4), warp tile 64x64, 3-stage cp.async pipeline.
// ---------------------------------------------------------------------------
__global__ __launch_bounds__(GEMM_THREADS, 1)
void gemm_mma_kernel(float* __restrict__ out) {
    extern __shared__ char smem[];
    const uint32_t sb = smem_u32(smem);
    const int tid  = threadIdx.x;
    const int wid  = tid >> 5;
    const int lane = tid & 31;
    const int wm   = wid & 1;          // 2 m-warps
    const int wn   = wid >> 1;         // 4 n-warps
    const int m0   = blockIdx.y * BM;
    const int n0   = blockIdx.x * BN;

    float acc[4][8][4];
#pragma unroll
    for (int a = 0; a < 4; a++)
#pragma unroll
        for (int b = 0; b < 8; b++)
#pragma unroll
            for (int c = 0; c < 4; c++) acc[a][b][c] = 0.0f;

    // ---- per-thread ldmatrix base offsets
    const int g = lane >> 3, r = lane & 7;
    // A: row = wm*64 + mt*16 + (g&1)*8 + r ; kloc = ks*16 + (g>>1)*8
    const uint32_t a_row_off = (uint32_t)((wm * 64 + (g & 1) * 8 + r) * 80);
    const uint32_t a_k_off   = (uint32_t)((g >> 1) * 16);
    // B: row = wn*64 + np*16 + (g>>1)*8 + r ; kloc = ks*16 + (g&1)*8
    const uint32_t b_row_off = (uint32_t)((wn * 64 + (g >> 1) * 8 + r) * 80);
    const uint32_t b_k_off   = (uint32_t)((g & 1) * 16);

    // ---- stage loader: 12 cp.async x 16B per thread
    auto load_stage = [&](int s, int kt) {
        const uint32_t st = sb + s * STAGE_SZ;
        const int krow = kt * BK;
#pragma unroll
        for (int it = 0; it < 2; it++) {
            int u = tid + it * 256, row = u >> 2, kc = u & 3;
            uint32_t so = (uint32_t)(row * 80 + kc * 16);
            const __nv_bfloat16* gh = g_x_hi + (size_t)(m0 + row) * IN_F + krow + kc * 8;
            const __nv_bfloat16* gl = g_x_lo + (size_t)(m0 + row) * IN_F + krow + kc * 8;
            CP16(st + A_HI_OFF + so, gh);
            CP16(st + A_LO_OFF + so, gl);
        }
#pragma unroll
        for (int it = 0; it < 4; it++) {
            int u = tid + it * 256, row = u >> 2, kc = u & 3;
            uint32_t so = (uint32_t)(row * 80 + kc * 16);
            const __nv_bfloat16* gh = g_w_hi + (size_t)(n0 + row) * IN_F + krow + kc * 8;
            const __nv_bfloat16* gl = g_w_lo + (size_t)(n0 + row) * IN_F + krow + kc * 8;
            CP16(st + B_HI_OFF + so, gh);
            CP16(st + B_LO_OFF + so, gl);
        }
        CP_COMMIT();
    };

    // ---- pipeline prologue: chunks 0 and 1 in flight
    load_stage(0, 0);
    load_stage(1, 1);

    const int NCH = IN_F / BK;   // 32
    for (int c = 0; c < NCH; c++) {
        if (c < NCH - 1) { CP_WAIT1(); } else { CP_WAIT0(); }
        __syncthreads();                       // chunk c resident; all warps past c-1
        if (c + 2 < NCH) load_stage((c + 2) % NSTAGE, c + 2);

        const uint32_t st = sb + (c % NSTAGE) * STAGE_SZ;
#pragma unroll
        for (int ks = 0; ks < 2; ks++) {
            uint32_t ah[4][4], al[4][4];
#pragma unroll
            for (int mt = 0; mt < 4; mt++) {
                uint32_t aaddr = st + a_row_off + (uint32_t)(mt * 1280) + a_k_off
                               + (uint32_t)(ks * 32);
                LDSM4(ah[mt][0], ah[mt][1], ah[mt][2], ah[mt][3], aaddr + A_HI_OFF);
                LDSM4(al[mt][0], al[mt][1], al[mt][2], al[mt][3], aaddr + A_LO_OFF);
            }
#pragma unroll
            for (int np = 0; np < 4; np++) {
                uint32_t bh[4], bl[4];
                uint32_t baddr = st + b_row_off + (uint32_t)(np * 1280) + b_k_off
                               + (uint32_t)(ks * 32);
                LDSM4(bh[0], bh[1], bh[2], bh[3], baddr + B_HI_OFF);
                LDSM4(bl[0], bl[1], bl[2], bl[3], baddr + B_LO_OFF);
#pragma unroll
                for (int mt = 0; mt < 4; mt++) {
                    mma16816(acc[mt][2 * np],     ah[mt], bh);
                    mma16816(acc[mt][2 * np],     ah[mt], bl);
                    mma16816(acc[mt][2 * np],     al[mt], bh);
                    mma16816(acc[mt][2 * np + 1], ah[mt], bh + 2);
                    mma16816(acc[mt][2 * np + 1], ah[mt], bl + 2);
                    mma16816(acc[mt][2 * np + 1], al[mt], bh + 2);
                }
            }
        }
        __syncthreads();                       // all warps done reading stage c
    }

    // ---- epilogue: c-frag layout m16n8: rows lane/4 & +8, cols 2*(lane%4)
    const int erow = lane >> 2;
    const int ecol = 2 * (lane & 3);
#pragma unroll
    for (int mt = 0; mt < 4; mt++) {
        const int mrow = m0 + wm * 64 + mt * 16 + erow;
#pragma unroll
        for (int j = 0; j < 8; j++) {
            const int col = n0 + wn * 64 + j * 8 + ecol;
            const float b0 = g_beff[col], b1 = g_beff[col + 1];
            float2 v0 = make_float2(acc[mt][j][0] + b0, acc[mt][j][1] + b1);
            float2 v1 = make_float2(acc[mt][j][2] + b0, acc[mt][j][3] + b1);
            *reinterpret_cast<float2*>(out + (size_t)mrow * OUT_F + col)       = v0;
            *reinterpret_cast<float2*>(out + (size_t)(mrow + 8) * OUT_F + col) = v1;
        }
    }
}

// ---------------------------------------------------------------------------
// Launch. Inputs identified BY ELEMENT COUNT (all unique, order-independent).
// fp16 inputs arrive as fp32 on device (confirmed R3).
// ---------------------------------------------------------------------------
extern "C" void kernel_launch(void* const* d_in, const int* in_sizes, int n_in,
                              void* d_out, int out_size) {
    const float *x = nullptr, *weight = nullptr, *bias = nullptr,
                *scale = nullptr, *wp = nullptr, *bp = nullptr;
    for (int i = 0; i < n_in; i++) {
        switch (in_sizes[i]) {
            case 16777216: x      = (const float*)d_in[i]; break;
            case 1048576:  weight = (const float*)d_in[i]; break;
            case 1024:     bias   = (const float*)d_in[i]; break;
            case 64:       scale  = (const float*)d_in[i]; break;
            case 67108864: wp     = (const float*)d_in[i]; break;
            case 65536:    bp     = (const float*)d_in[i]; break;
            default: break;
        }
    }
    float* out = (float*)d_out;

    cudaFuncSetAttribute(gemm_mma_kernel,
                         cudaFuncAttributeMaxDynamicSharedMemorySize, SMEM_TOTAL);

    reduce_weight_kernel<<<(OUT_F * IN_F) / 4 / 256, 256>>>(weight, scale, wp);
    split_x_kernel<<<((size_t)MROWS * IN_F) / 8 / 256, 256>>>(x);
    reduce_bias_kernel<<<(OUT_F + 255) / 256, 256>>>(bias, scale, bp);

    dim3 grid(OUT_F / BN, MROWS / BM);   // (4, 128) = 512 CTAs
    gemm_mma_kernel<<<grid, GEMM_THREADS, SMEM_TOTAL>>>(out);
}

// round 6
// speedup vs baseline: 5.8828x; 1.8971x over previous
#include <cuda_runtime.h>
#include <cuda_fp16.h>
#include <cstdint>
#include <cstddef>

#define IN_F   1024
#define OUT_F  1024
#define POP    64
#define MROWS  16384

#define BM 128
#define BN 256
#define BK 32
#define GEMM_THREADS 512
#define NCH (IN_F / BK)            // 32 k-chunks

// smem stage layout: bf16/fp16 rows of 32 elems + 8 pad = 80B stride
// (80B = 20 words -> 8-row ldmatrix phases hit 8 distinct banks; conflict-free)
#define A_OFF    0                 // 128 rows x 80B = 10240
#define B_OFF    10240             // 256 rows x 80B = 20480
#define STAGE_SZ 30720
#define NSTAGE   4
#define SMEM_TOTAL (NSTAGE * STAGE_SZ)   // 122880 B

// ---------------- scratch (device globals; allocation is forbidden) --------
__device__ __align__(16) __half g_x[(size_t)MROWS * IN_F];
__device__ __align__(16) __half g_w[(size_t)OUT_F * IN_F];
__device__ float g_beff[OUT_F];

// ---------------- PTX helpers (portable to plain sm_103 target) ------------
__device__ __forceinline__ uint32_t smem_u32(const void* p) {
    uint32_t a;
    asm("{ .reg .u64 t; cvta.to.shared.u64 t, %1; cvt.u32.u64 %0, t; }" : "=r"(a) : "l"(p));
    return a;
}
#define CP16(dst_u32, gptr) \
    asm volatile("cp.async.cg.shared.global [%0], [%1], 16;" :: "r"(dst_u32), "l"(gptr) : "memory")
#define CP_COMMIT() asm volatile("cp.async.commit_group;" ::: "memory")
#define CP_WAIT2()  asm volatile("cp.async.wait_group 2;" ::: "memory")
#define CP_WAIT1()  asm volatile("cp.async.wait_group 1;" ::: "memory")
#define CP_WAIT0()  asm volatile("cp.async.wait_group 0;" ::: "memory")

#define LDSM4(r0, r1, r2, r3, addr)                                              \
    asm volatile("ldmatrix.sync.aligned.m8n8.x4.shared.b16 {%0,%1,%2,%3}, [%4];" \
        : "=r"(r0), "=r"(r1), "=r"(r2), "=r"(r3) : "r"(addr))

__device__ __forceinline__ void mma16816(float* d, const uint32_t* a, const uint32_t* b) {
    asm volatile(
        "mma.sync.aligned.m16n8k16.row.col.f32.f16.f16.f32 "
        "{%0,%1,%2,%3}, {%4,%5,%6,%7}, {%8,%9}, {%0,%1,%2,%3};"
        : "+f"(d[0]), "+f"(d[1]), "+f"(d[2]), "+f"(d[3])
        : "r"(a[0]), "r"(a[1]), "r"(a[2]), "r"(a[3]), "r"(b[0]), "r"(b[1]));
}

// ---------------------------------------------------------------------------
// Prep 1: w_eff = weight + sum_i s_i*wp_i (fp32 math), emitted as fp16
// ---------------------------------------------------------------------------
__global__ void reduce_weight_kernel(const float* __restrict__ weight,
                                     const float* __restrict__ scale,
                                     const float* __restrict__ wp) {
    __shared__ float s_scale[POP];
    if (threadIdx.x < POP) s_scale[threadIdx.x] = scale[threadIdx.x];
    __syncthreads();

    size_t base = ((size_t)blockIdx.x * blockDim.x + threadIdx.x) * 4;
    float4 acc = *reinterpret_cast<const float4*>(weight + base);
#pragma unroll 8
    for (int i = 0; i < POP; i++) {
        const float s = s_scale[i];
        float4 p = *reinterpret_cast<const float4*>(wp + (size_t)i * (OUT_F * IN_F) + base);
        acc.x += s * p.x; acc.y += s * p.y; acc.z += s * p.z; acc.w += s * p.w;
    }
    __half h[4] = {__float2half_rn(acc.x), __float2half_rn(acc.y),
                   __float2half_rn(acc.z), __float2half_rn(acc.w)};
    *reinterpret_cast<uint2*>(g_w + base) = *reinterpret_cast<uint2*>(h);
}

// ---------------------------------------------------------------------------
// Prep 2: x -> fp16
// ---------------------------------------------------------------------------
__global__ void convert_x_kernel(const float* __restrict__ x) {
    size_t base = ((size_t)blockIdx.x * blockDim.x + threadIdx.x) * 8;
    float4 a = *reinterpret_cast<const float4*>(x + base);
    float4 b = *reinterpret_cast<const float4*>(x + base + 4);
    __half h[8] = {__float2half_rn(a.x), __float2half_rn(a.y),
                   __float2half_rn(a.z), __float2half_rn(a.w),
                   __float2half_rn(b.x), __float2half_rn(b.y),
                   __float2half_rn(b.z), __float2half_rn(b.w)};
    *reinterpret_cast<uint4*>(g_x + base) = *reinterpret_cast<uint4*>(h);
}

// ---------------------------------------------------------------------------
// Prep 3: bias
// ---------------------------------------------------------------------------
__global__ void reduce_bias_kernel(const float* __restrict__ bias,
                                   const float* __restrict__ scale,
                                   const float* __restrict__ bp) {
    int j = blockIdx.x * blockDim.x + threadIdx.x;
    if (j >= OUT_F) return;
    float acc = bias[j];
#pragma unroll 8
    for (int i = 0; i < POP; i++) acc += scale[i] * bp[i * OUT_F + j];
    g_beff[j] = acc;
}

// ---------------------------------------------------------------------------
// GEMM via mma.sync fp16 single-pass: out = x @ w_eff^T + b_eff (fp32 acc)
// CTA 128x256x32, 512 threads (16 warps, 2x8), warp tile 64x32,
// 4-stage cp.async pipeline, one barrier per k-chunk.
// ---------------------------------------------------------------------------
__global__ __launch_bounds__(GEMM_THREADS, 1)
void gemm_mma_kernel(float* __restrict__ out) {
    extern __shared__ char smem[];
    const uint32_t sb = smem_u32(smem);
    const int tid  = threadIdx.x;
    const int wid  = tid >> 5;
    const int lane = tid & 31;
    const int wm   = wid & 1;          // 2 m-warps (64 rows each)
    const int wn   = wid >> 1;         // 8 n-warps (32 cols each)
    const int m0   = blockIdx.y * BM;
    const int n0   = blockIdx.x * BN;

    float acc[4][4][4];
#pragma unroll
    for (int a = 0; a < 4; a++)
#pragma unroll
        for (int b = 0; b < 4; b++)
#pragma unroll
            for (int c = 0; c < 4; c++) acc[a][b][c] = 0.0f;

    // ---- per-thread ldmatrix base offsets (fragment maps validated in R4)
    const int g = lane >> 3, r = lane & 7;
    const uint32_t a_row_off = (uint32_t)((wm * 64 + (g & 1) * 8 + r) * 80);
    const uint32_t a_k_off   = (uint32_t)((g >> 1) * 16);
    const uint32_t b_row_off = (uint32_t)((wn * 32 + (g >> 1) * 8 + r) * 80);
    const uint32_t b_k_off   = (uint32_t)((g & 1) * 16);

    // ---- stage loader: 3 cp.async x 16B per thread (A: 512 units, B: 1024)
    auto load_stage = [&](int s, int kt) {
        const uint32_t st = sb + s * STAGE_SZ;
        const int krow = kt * BK;
        {
            int row = tid >> 2, kc = tid & 3;
            CP16(st + A_OFF + (uint32_t)(row * 80 + kc * 16),
                 g_x + (size_t)(m0 + row) * IN_F + krow + kc * 8);
        }
#pragma unroll
        for (int it = 0; it < 2; it++) {
            int u = tid + it * 512, row = u >> 2, kc = u & 3;
            CP16(st + B_OFF + (uint32_t)(row * 80 + kc * 16),
                 g_w + (size_t)(n0 + row) * IN_F + krow + kc * 8);
        }
        CP_COMMIT();
    };

    // ---- pipeline prologue: 3 stages in flight
    load_stage(0, 0);
    load_stage(1, 1);
    load_stage(2, 2);

    for (int c = 0; c < NCH; c++) {
        if (c + 3 <= NCH)      { CP_WAIT2(); }
        else if (c + 2 <= NCH) { CP_WAIT1(); }
        else                   { CP_WAIT0(); }
        __syncthreads();                       // chunk c resident; stage (c+3)%4 free
        if (c + 3 < NCH) load_stage((c + 3) % NSTAGE, c + 3);

        const uint32_t st = sb + (c % NSTAGE) * STAGE_SZ;
#pragma unroll
        for (int ks = 0; ks < 2; ks++) {
            uint32_t ah[4][4];
#pragma unroll
            for (int mt = 0; mt < 4; mt++) {
                uint32_t aaddr = st + A_OFF + a_row_off + (uint32_t)(mt * 1280)
                               + a_k_off + (uint32_t)(ks * 32);
                LDSM4(ah[mt][0], ah[mt][1], ah[mt][2], ah[mt][3], aaddr);
            }
#pragma unroll
            for (int np = 0; np < 2; np++) {
                uint32_t bh[4];
                uint32_t baddr = st + B_OFF + b_row_off + (uint32_t)(np * 1280)
                               + b_k_off + (uint32_t)(ks * 32);
                LDSM4(bh[0], bh[1], bh[2], bh[3], baddr);
#pragma unroll
                for (int mt = 0; mt < 4; mt++) {
                    mma16816(acc[mt][2 * np],     ah[mt], bh);
                    mma16816(acc[mt][2 * np + 1], ah[mt], bh + 2);
                }
            }
        }
    }

    // ---- epilogue: c-frag m16n8 layout: rows lane/4 & +8, cols 2*(lane%4)
    const int erow = lane >> 2;
    const int ecol = 2 * (lane & 3);
#pragma unroll
    for (int mt = 0; mt < 4; mt++) {
        const int mrow = m0 + wm * 64 + mt * 16 + erow;
#pragma unroll
        for (int j = 0; j < 4; j++) {
            const int col = n0 + wn * 32 + j * 8 + ecol;
            const float b0 = g_beff[col], b1 = g_beff[col + 1];
            float2 v0 = make_float2(acc[mt][j][0] + b0, acc[mt][j][1] + b1);
            float2 v1 = make_float2(acc[mt][j][2] + b0, acc[mt][j][3] + b1);
            *reinterpret_cast<float2*>(out + (size_t)mrow * OUT_F + col)       = v0;
            *reinterpret_cast<float2*>(out + (size_t)(mrow + 8) * OUT_F + col) = v1;
        }
    }
}

// ---------------------------------------------------------------------------
// Launch. Inputs identified BY ELEMENT COUNT (all unique, order-independent).
// fp16 inputs arrive as fp32 on device (confirmed R3).
// ---------------------------------------------------------------------------
extern "C" void kernel_launch(void* const* d_in, const int* in_sizes, int n_in,
                              void* d_out, int out_size) {
    const float *x = nullptr, *weight = nullptr, *bias = nullptr,
                *scale = nullptr, *wp = nullptr, *bp = nullptr;
    for (int i = 0; i < n_in; i++) {
        switch (in_sizes[i]) {
            case 16777216: x      = (const float*)d_in[i]; break;
            case 1048576:  weight = (const float*)d_in[i]; break;
            case 1024:     bias   = (const float*)d_in[i]; break;
            case 64:       scale  = (const float*)d_in[i]; break;
            case 67108864: wp     = (const float*)d_in[i]; break;
            case 65536:    bp     = (const float*)d_in[i]; break;
            default: break;
        }
    }
    float* out = (float*)d_out;

    cudaFuncSetAttribute(gemm_mma_kernel,
                         cudaFuncAttributeMaxDynamicSharedMemorySize, SMEM_TOTAL);

    reduce_weight_kernel<<<(OUT_F * IN_F) / 4 / 256, 256>>>(weight, scale, wp);
    convert_x_kernel<<<((size_t)MROWS * IN_F) / 8 / 256, 256>>>(x);
    reduce_bias_kernel<<<(OUT_F + 255) / 256, 256>>>(bias, scale, bp);

    dim3 grid(OUT_F / BN, MROWS / BM);   // (4, 128) = 512 CTAs
    gemm_mma_kernel<<<grid, GEMM_THREADS, SMEM_TOTAL>>>(out);
}